// round 1
// baseline (speedup 1.0000x reference)
#include <cuda_runtime.h>
#include <math.h>

#define BATCH   64
#define DIMC    64
#define HEADS   8
#define DHEAD   64
#define INNER   512
#define MLPD    256
#define DEPTH   4
#define NPATCH  225
#define NTOK    226
#define M2      (2*BATCH*NTOK)   /* 28928 rows (both branches) */
#define EPSV    1e-5f
#define SCALEV  0.125f           /* 64^-0.5 */

/* ---------------- scratch (no allocs allowed) ---------------- */
__device__ float g_X [(size_t)M2*DIMC];
__device__ float g_XN[(size_t)M2*DIMC];
__device__ float g_Q [(size_t)M2*INNER];   /* also holds attention output in-place */
__device__ float g_V [(size_t)M2*INNER];
__device__ float g_H [(size_t)M2*MLPD];
__device__ float g_sdfm[BATCH*DIMC];       /* sqrt(sigmoid(..)*SCALE) */
__device__ float g_xmean[BATCH*2*DIMC];

/* ---------------- prologue kernels ---------------- */
__global__ void mean_kernel(const float* __restrict__ hsi, const float* __restrict__ lidar) {
    int idx = blockIdx.x*blockDim.x + threadIdx.x;
    if (idx >= BATCH*128) return;
    int b = idx >> 7, c = idx & 127;
    const float* src = (c < 64) ? (hsi   + ((size_t)b*64 + c)    *NPATCH)
                                : (lidar + ((size_t)b*64 + (c-64))*NPATCH);
    float s = 0.f;
    for (int p = 0; p < NPATCH; p++) s += src[p];
    g_xmean[idx] = s * (1.0f/NPATCH);
}

__global__ void dfm_kernel(const float* __restrict__ fmg_w) {
    int idx = blockIdx.x*blockDim.x + threadIdx.x;
    if (idx >= BATCH*64) return;
    int b = idx >> 6, d = idx & 63;
    const float* xm = g_xmean + b*128;
    const float* wc = fmg_w + d*65;        /* column d*64+d, row stride 4096 */
    float s = 0.f;
    for (int c = 0; c < 128; c++) s += xm[c] * wc[(size_t)c*4096];
    float sig = 1.0f/(1.0f + expf(-s));
    g_sdfm[idx] = sqrtf(sig * SCALEV);
}

__global__ void build_kernel(const float* __restrict__ hsi,
                             const float* __restrict__ cls_hsi, const float* __restrict__ cls_lidar,
                             const float* __restrict__ pos_hsi, const float* __restrict__ pos_lidar) {
    int idx = blockIdx.x*blockDim.x + threadIdx.x;
    if (idx >= M2*DIMC) return;
    int c  = idx & 63;
    int n  = (idx >> 6) % NTOK;
    int bp = idx / (NTOK*64);
    int b  = bp & 63;
    int br = bp >> 6;                       /* 0 = hsi branch, 1 = lidar branch */
    const float* cls = br ? cls_lidar : cls_hsi;
    const float* pos = br ? pos_lidar : pos_hsi;
    /* bug-faithful: BOTH branches use h_e (hsi) patch embeddings */
    float v = (n == 0) ? cls[c] : hsi[((size_t)b*64 + c)*NPATCH + (n-1)];
    g_X[idx] = v + pos[n*64 + c];
}

/* ---------------- layernorm: one warp per row ---------------- */
__global__ void ln_kernel(const float* __restrict__ Xp, float* __restrict__ XNp,
                          const float* __restrict__ g, const float* __restrict__ bb) {
    int w = threadIdx.x >> 5, lane = threadIdx.x & 31;
    int row = blockIdx.x*8 + w;
    const float* xr = Xp + (size_t)row*64;
    float x0 = xr[lane], x1 = xr[lane+32];
    float s = x0 + x1;
    #pragma unroll
    for (int o = 16; o; o >>= 1) s += __shfl_xor_sync(0xffffffffu, s, o);
    float m = s * (1.0f/64.0f);
    float d0 = x0 - m, d1 = x1 - m;
    float v = d0*d0 + d1*d1;
    #pragma unroll
    for (int o = 16; o; o >>= 1) v += __shfl_xor_sync(0xffffffffu, v, o);
    float r = rsqrtf(v*(1.0f/64.0f) + EPSV);
    XNp[(size_t)row*64 + lane]      = d0*r*g[lane]    + bb[lane];
    XNp[(size_t)row*64 + lane + 32] = d1*r*g[lane+32] + bb[lane+32];
}

/* ---------------- tiled fp32 GEMM: C[128 x BN] tile, BK=32 ----------------
   A: [M,K] (lda=K), W: [K,*] (ldw), C: [M,*] (ldc). Optional bias/GELU/accumulate. */
template<int TN, bool GELU_, bool ACC_, bool BIAS_>
__global__ void __launch_bounds__(256) gemm_kernel(
    const float* __restrict__ A, const float* __restrict__ W,
    const float* __restrict__ bias, float* __restrict__ C,
    int K, int ldw, int ldc)
{
    constexpr int BN = 16*TN;
    __shared__ float As[128*33];
    __shared__ float Bs[32*BN];
    int t  = threadIdx.x;
    int tc = t & 15;          /* n direction (low bits -> coalesced epilogue) */
    int tr = t >> 4;          /* m direction */
    int m0 = blockIdx.y * 128;
    int n0 = blockIdx.x * BN;

    float acc[8][TN];
    #pragma unroll
    for (int i = 0; i < 8; i++)
        #pragma unroll
        for (int j = 0; j < TN; j++) acc[i][j] = 0.f;

    for (int kk = 0; kk < K; kk += 32) {
        /* A tile 128x32 -> As[m][k], pad 33 (conflict-free store & read) */
        #pragma unroll
        for (int it = 0; it < 4; it++) {
            int f = t + it*256;
            int am = f >> 3, ak = (f & 7)*4;
            float4 v4 = *(const float4*)(A + (size_t)(m0+am)*K + kk + ak);
            float* dst = &As[am*33 + ak];
            dst[0]=v4.x; dst[1]=v4.y; dst[2]=v4.z; dst[3]=v4.w;
        }
        /* W tile 32xBN -> Bs[k][n] */
        #pragma unroll
        for (int it = 0; it < BN/32; it++) {
            int f = t + it*256;
            int wk, wn;
            if (BN == 128) { wk = f >> 5; wn = (f & 31)*4; }
            else           { wk = f >> 4; wn = (f & 15)*4; }
            *(float4*)&Bs[wk*BN + wn] = *(const float4*)(W + (size_t)(kk+wk)*ldw + n0 + wn);
        }
        __syncthreads();
        #pragma unroll
        for (int k = 0; k < 32; k++) {
            float a[8];
            #pragma unroll
            for (int i = 0; i < 8; i++) a[i] = As[(tr + 16*i)*33 + k];
            float bf[TN];
            #pragma unroll
            for (int jv = 0; jv < TN; jv += 4) {
                float4 b4 = *(float4*)&Bs[k*BN + tc*TN + jv];
                bf[jv]=b4.x; bf[jv+1]=b4.y; bf[jv+2]=b4.z; bf[jv+3]=b4.w;
            }
            #pragma unroll
            for (int i = 0; i < 8; i++)
                #pragma unroll
                for (int j = 0; j < TN; j++) acc[i][j] += a[i]*bf[j];
        }
        __syncthreads();
    }

    float bias4[TN];
    if (BIAS_) {
        #pragma unroll
        for (int jv = 0; jv < TN; jv += 4)
            *(float4*)&bias4[jv] = *(const float4*)(bias + n0 + tc*TN + jv);
    }
    #pragma unroll
    for (int i = 0; i < 8; i++) {
        int m = m0 + tr + 16*i;
        float* cp = C + (size_t)m*ldc + n0 + tc*TN;
        #pragma unroll
        for (int jv = 0; jv < TN; jv += 4) {
            float4 r;
            float vv[4];
            #pragma unroll
            for (int j = 0; j < 4; j++) {
                float x = acc[i][jv+j];
                if (BIAS_) x += bias4[jv+j];
                if (GELU_) x = 0.5f*x*(1.0f + erff(x*0.70710678118654752f));
                vv[j] = x;
            }
            if (ACC_) {
                float4 old = *(float4*)(cp + jv);
                vv[0]+=old.x; vv[1]+=old.y; vv[2]+=old.z; vv[3]+=old.w;
            }
            r.x=vv[0]; r.y=vv[1]; r.z=vv[2]; r.w=vv[3];
            *(float4*)(cp + jv) = r;
        }
    }
}

/* ---------------- fused attention per (batch', head) ----------------
   qt = q * sqrt(dfm*SCALE) staged in smem (256 rows, zero padded),
   v staged in smem. dots = qt qt^T, softmax, O = P V, written in-place over Q. */
#define QROWS   256
#define QPAD    65
#define VFLOATS 14692              /* 226*65 rounded up to 16B multiple */
#define PWSZ    912                /* per-warp p buffer, 16B aligned */
#define ATT_SMEM_FLOATS (QROWS*QPAD + VFLOATS + 8*PWSZ)
#define ATT_SMEM_BYTES  (ATT_SMEM_FLOATS*4)

__global__ void __launch_bounds__(256) attn_kernel() {
    extern __shared__ float sm[];
    float* qsm  = sm;
    float* vsm  = sm + QROWS*QPAD;
    float* pbuf = vsm + VFLOATS;

    int t = threadIdx.x;
    int w = t >> 5, lane = t & 31;
    int bh = blockIdx.x;
    int bp = bh >> 3, h = bh & 7;
    int bidx = bp & 63;
    float* Qb = g_Q + (size_t)bp*NTOK*INNER + h*DHEAD;
    const float* Vb = g_V + (size_t)bp*NTOK*INNER + h*DHEAD;

    /* load qt (scaled) and v into smem, pad 65 per row */
    {
        int d4 = (t & 15)*4;
        float4 sd = *(const float4*)&g_sdfm[bidx*64 + d4];
        for (int f = t; f < QROWS*16; f += 256) {
            int n = f >> 4;
            float4 qv = make_float4(0.f,0.f,0.f,0.f);
            if (n < NTOK) qv = *(const float4*)(Qb + (size_t)n*INNER + d4);
            float* dst = &qsm[n*QPAD + d4];
            dst[0]=qv.x*sd.x; dst[1]=qv.y*sd.y; dst[2]=qv.z*sd.z; dst[3]=qv.w*sd.w;
        }
        for (int f = t; f < NTOK*16; f += 256) {
            int n = f >> 4;
            float4 vv = *(const float4*)(Vb + (size_t)n*INNER + d4);
            float* dst = &vsm[n*QPAD + d4];
            dst[0]=vv.x; dst[1]=vv.y; dst[2]=vv.z; dst[3]=vv.w;
        }
    }
    __syncthreads();

    float* pw = pbuf + w*PWSZ;

    for (int i0 = w*4; i0 < NTOK; i0 += 32) {
        float acc[4][8];
        #pragma unroll
        for (int ii = 0; ii < 4; ii++)
            #pragma unroll
            for (int jj = 0; jj < 8; jj++) acc[ii][jj] = 0.f;

        /* dots: 4 query rows x 8 key cols per lane */
        #pragma unroll 2
        for (int d = 0; d < 64; d++) {
            float qi[4];
            #pragma unroll
            for (int ii = 0; ii < 4; ii++) qi[ii] = qsm[(i0+ii)*QPAD + d];
            #pragma unroll
            for (int jj = 0; jj < 8; jj++) {
                float qj = qsm[(lane + 32*jj)*QPAD + d];
                #pragma unroll
                for (int ii = 0; ii < 4; ii++) acc[ii][jj] += qi[ii]*qj;
            }
        }
        /* mask padded keys j >= 226 (only jj==7, lane>=2) */
        if (lane + 224 >= NTOK) {
            #pragma unroll
            for (int ii = 0; ii < 4; ii++) acc[ii][7] = -1e30f;
        }
        /* softmax per query row */
        #pragma unroll
        for (int ii = 0; ii < 4; ii++) {
            float mx = acc[ii][0];
            #pragma unroll
            for (int jj = 1; jj < 8; jj++) mx = fmaxf(mx, acc[ii][jj]);
            #pragma unroll
            for (int o = 16; o; o >>= 1) mx = fmaxf(mx, __shfl_xor_sync(0xffffffffu, mx, o));
            float s = 0.f;
            #pragma unroll
            for (int jj = 0; jj < 8; jj++) { float p = expf(acc[ii][jj]-mx); acc[ii][jj]=p; s += p; }
            #pragma unroll
            for (int o = 16; o; o >>= 1) s += __shfl_xor_sync(0xffffffffu, s, o);
            float inv = 1.0f/s;
            #pragma unroll
            for (int jj = 0; jj < 8; jj++) acc[ii][jj] *= inv;
        }
        /* transpose p via smem */
        #pragma unroll
        for (int jj = 0; jj < 8; jj++) {
            int j = lane + 32*jj;
            if (j < NTOK) {
                #pragma unroll
                for (int ii = 0; ii < 4; ii++) pw[j*4 + ii] = acc[ii][jj];
            }
        }
        __syncwarp();
        /* O = P V : lane owns dims (lane, lane+32) */
        float o0[4] = {0.f,0.f,0.f,0.f}, o1[4] = {0.f,0.f,0.f,0.f};
        for (int j = 0; j < NTOK; j++) {
            float p4[4];
            *(float4*)p4 = *(float4*)&pw[j*4];
            float v0 = vsm[j*QPAD + lane];
            float v1 = vsm[j*QPAD + 32 + lane];
            #pragma unroll
            for (int ii = 0; ii < 4; ii++) { o0[ii] += p4[ii]*v0; o1[ii] += p4[ii]*v1; }
        }
        #pragma unroll
        for (int ii = 0; ii < 4; ii++) {
            int i = i0 + ii;
            if (i < NTOK) {
                Qb[(size_t)i*INNER + lane]      = o0[ii];
                Qb[(size_t)i*INNER + 32 + lane] = o1[ii];
            }
        }
        __syncwarp();
    }
}

/* ---------------- token exchange + final ---------------- */
__global__ void swap_cls_kernel() {
    int idx = blockIdx.x*blockDim.x + threadIdx.x;
    if (idx >= BATCH*64) return;
    int b = idx >> 6, c = idx & 63;
    size_t i0 = (size_t)b*NTOK*64 + c;
    size_t i1 = (size_t)(b+BATCH)*NTOK*64 + c;
    float a = g_X[i0], d = g_X[i1];
    g_X[i0] = d; g_X[i1] = a;
}

__global__ void final_kernel(float* __restrict__ out) {
    int idx = blockIdx.x*blockDim.x + threadIdx.x;
    if (idx >= BATCH*64) return;
    int b = idx >> 6, c = idx & 63;
    out[idx] = g_X[(size_t)b*NTOK*64 + c] + g_X[(size_t)(b+BATCH)*NTOK*64 + c];
}

/* ---------------- host orchestration ---------------- */
extern "C" void kernel_launch(void* const* d_in, const int* in_sizes, int n_in,
                              void* d_out, int out_size)
{
    const float* hsi       = (const float*)d_in[0];
    const float* lidar     = (const float*)d_in[1];
    const float* cls_hsi   = (const float*)d_in[2];
    const float* cls_lidar = (const float*)d_in[3];
    const float* pos_hsi   = (const float*)d_in[4];
    const float* pos_lidar = (const float*)d_in[5];
    const float* fmg_w     = (const float*)d_in[6];
    const float* ln1_g     = (const float*)d_in[7];
    const float* ln1_b     = (const float*)d_in[8];
    const float* qkv_w     = (const float*)d_in[9];
    const float* out_w     = (const float*)d_in[10];
    const float* out_b     = (const float*)d_in[11];
    const float* ln2_g     = (const float*)d_in[12];
    const float* ln2_b     = (const float*)d_in[13];
    const float* ff_w1     = (const float*)d_in[14];
    const float* ff_b1     = (const float*)d_in[15];
    const float* ff_w2     = (const float*)d_in[16];
    const float* ff_b2     = (const float*)d_in[17];

    float *X, *XN, *Q, *V, *H;
    cudaGetSymbolAddress((void**)&X,  g_X);
    cudaGetSymbolAddress((void**)&XN, g_XN);
    cudaGetSymbolAddress((void**)&Q,  g_Q);
    cudaGetSymbolAddress((void**)&V,  g_V);
    cudaGetSymbolAddress((void**)&H,  g_H);

    cudaFuncSetAttribute(attn_kernel, cudaFuncAttributeMaxDynamicSharedMemorySize, ATT_SMEM_BYTES);

    mean_kernel<<<32, 256>>>(hsi, lidar);
    dfm_kernel<<<16, 256>>>(fmg_w);
    build_kernel<<<(M2*DIMC + 255)/256, 256>>>(hsi, cls_hsi, cls_lidar, pos_hsi, pos_lidar);

    for (int phase = 0; phase < 2; phase++) {
        for (int L = 0; L < DEPTH; L++) {
            ln_kernel<<<M2/8, 256>>>(X, XN, ln1_g + L*64, ln1_b + L*64);
            /* Q projection: qkv cols [0,512) ; V projection: cols [1024,1536) (K unused) */
            gemm_kernel<8,false,false,false><<<dim3(4,226), 256>>>(
                XN, qkv_w + (size_t)L*64*1536,        nullptr, Q, 64, 1536, 512);
            gemm_kernel<8,false,false,false><<<dim3(4,226), 256>>>(
                XN, qkv_w + (size_t)L*64*1536 + 1024, nullptr, V, 64, 1536, 512);
            attn_kernel<<<1024, 256, ATT_SMEM_BYTES>>>();
            gemm_kernel<4,false,true,true><<<dim3(1,226), 256>>>(
                Q, out_w + (size_t)L*512*64, out_b + L*64, X, 512, 64, 64);
            ln_kernel<<<M2/8, 256>>>(X, XN, ln2_g + L*64, ln2_b + L*64);
            gemm_kernel<8,true,false,true><<<dim3(2,226), 256>>>(
                XN, ff_w1 + (size_t)L*64*256, ff_b1 + L*256, H, 64, 256, 256);
            gemm_kernel<4,false,true,true><<<dim3(1,226), 256>>>(
                H, ff_w2 + (size_t)L*256*64, ff_b2 + L*64, X, 256, 64, 64);
        }
        if (phase == 0) swap_cls_kernel<<<16, 256>>>();
    }
    final_kernel<<<16, 256>>>((float*)d_out);
}

// round 2
// speedup vs baseline: 1.8574x; 1.8574x over previous
#include <cuda_runtime.h>
#include <math.h>

#define BATCH   64
#define DIMC    64
#define HEADS   8
#define DHEAD   64
#define INNER   512
#define MLPD    256
#define DEPTH   4
#define NPATCH  225
#define NTOK    226
#define M2      (2*BATCH*NTOK)   /* 28928 rows (both branches) */
#define EPSV    1e-5f
#define SCALEV  0.125f           /* 64^-0.5 */

/* ---------------- packed f32x2 helpers ---------------- */
typedef unsigned long long u64t;

__device__ __forceinline__ u64t dup2(float x) {
    u64t r;
    asm("mov.b64 %0, {%1, %1};" : "=l"(r) : "r"(__float_as_uint(x)));
    return r;
}
__device__ __forceinline__ void fma2(u64t& d, u64t a, u64t b) {
    asm("fma.rn.f32x2 %0, %1, %2, %0;" : "+l"(d) : "l"(a), "l"(b));
}
__device__ __forceinline__ float2 unpack2(u64t v) {
    unsigned lo, hi;
    asm("mov.b64 {%0, %1}, %2;" : "=r"(lo), "=r"(hi) : "l"(v));
    return make_float2(__uint_as_float(lo), __uint_as_float(hi));
}

/* ---------------- scratch (no allocs allowed) ---------------- */
__device__ float g_X [(size_t)M2*DIMC];
__device__ float g_XN[(size_t)M2*DIMC];
__device__ float g_Q [(size_t)M2*INNER];   /* also holds attention output in-place */
__device__ float g_V [(size_t)M2*INNER];
__device__ float g_H [(size_t)M2*MLPD];
__device__ float g_sdfm[BATCH*DIMC];       /* sqrt(sigmoid(..)*SCALE) */
__device__ float g_xmean[BATCH*2*DIMC];

/* ---------------- prologue kernels ---------------- */
__global__ void mean_kernel(const float* __restrict__ hsi, const float* __restrict__ lidar) {
    int idx = blockIdx.x*blockDim.x + threadIdx.x;
    if (idx >= BATCH*128) return;
    int b = idx >> 7, c = idx & 127;
    const float* src = (c < 64) ? (hsi   + ((size_t)b*64 + c)    *NPATCH)
                                : (lidar + ((size_t)b*64 + (c-64))*NPATCH);
    float s = 0.f;
    for (int p = 0; p < NPATCH; p++) s += src[p];
    g_xmean[idx] = s * (1.0f/NPATCH);
}

__global__ void dfm_kernel(const float* __restrict__ fmg_w) {
    int idx = blockIdx.x*blockDim.x + threadIdx.x;
    if (idx >= BATCH*64) return;
    int b = idx >> 6, d = idx & 63;
    const float* xm = g_xmean + b*128;
    const float* wc = fmg_w + d*65;        /* column d*64+d, row stride 4096 */
    float s = 0.f;
    for (int c = 0; c < 128; c++) s += xm[c] * wc[(size_t)c*4096];
    float sig = 1.0f/(1.0f + expf(-s));
    g_sdfm[idx] = sqrtf(sig * SCALEV);
}

__global__ void build_kernel(const float* __restrict__ hsi,
                             const float* __restrict__ cls_hsi, const float* __restrict__ cls_lidar,
                             const float* __restrict__ pos_hsi, const float* __restrict__ pos_lidar) {
    int idx = blockIdx.x*blockDim.x + threadIdx.x;
    if (idx >= M2*DIMC) return;
    int c  = idx & 63;
    int n  = (idx >> 6) % NTOK;
    int bp = idx / (NTOK*64);
    int b  = bp & 63;
    int br = bp >> 6;                       /* 0 = hsi branch, 1 = lidar branch */
    const float* cls = br ? cls_lidar : cls_hsi;
    const float* pos = br ? pos_lidar : pos_hsi;
    /* bug-faithful: BOTH branches use h_e (hsi) patch embeddings */
    float v = (n == 0) ? cls[c] : hsi[((size_t)b*64 + c)*NPATCH + (n-1)];
    g_X[idx] = v + pos[n*64 + c];
}

/* ---------------- layernorm: one warp per row ---------------- */
__global__ void ln_kernel(const float* __restrict__ Xp, float* __restrict__ XNp,
                          const float* __restrict__ g, const float* __restrict__ bb) {
    int w = threadIdx.x >> 5, lane = threadIdx.x & 31;
    int row = blockIdx.x*8 + w;
    const float* xr = Xp + (size_t)row*64;
    float x0 = xr[lane], x1 = xr[lane+32];
    float s = x0 + x1;
    #pragma unroll
    for (int o = 16; o; o >>= 1) s += __shfl_xor_sync(0xffffffffu, s, o);
    float m = s * (1.0f/64.0f);
    float d0 = x0 - m, d1 = x1 - m;
    float v = d0*d0 + d1*d1;
    #pragma unroll
    for (int o = 16; o; o >>= 1) v += __shfl_xor_sync(0xffffffffu, v, o);
    float r = rsqrtf(v*(1.0f/64.0f) + EPSV);
    XNp[(size_t)row*64 + lane]      = d0*r*g[lane]    + bb[lane];
    XNp[(size_t)row*64 + lane + 32] = d1*r*g[lane+32] + bb[lane+32];
}

/* ---------------- tiled f32x2 GEMM ----------------
   A: [M,K] row-major (lda=K), W: [K,*] (ldw), C: [M,*] (ldc).
   BM x BN tile, BK=32. A staged k-major in smem so per-thread row pairs are
   contiguous 64-bit loads; packed fma.rn.f32x2 accumulators.
   QV_: grid.x=8, blocks 0-3 -> Q (w cols n0), 4-7 -> V (w cols 1024+n0). */
template<int BM, int TN, bool GELU_, bool ACC_, bool BIAS_, bool QV_>
__global__ void __launch_bounds__(256) gemm_kernel(
    const float* __restrict__ A, const float* __restrict__ W,
    const float* __restrict__ bias, float* __restrict__ C, float* __restrict__ C2,
    int K, int ldw, int ldc)
{
    constexpr int BN  = 16*TN;
    constexpr int RM  = BM/16;
    constexpr int LDA = BM + 2;
    __shared__ float As[32*LDA];
    __shared__ float Bs[32*BN];
    int t  = threadIdx.x;
    int tc = t & 15;
    int tr = t >> 4;
    int m0 = blockIdx.y * BM;

    int n0, wn0;
    float* Cp;
    if (QV_) {
        int nb = blockIdx.x;
        bool isV = nb >= 4;
        n0  = (isV ? nb-4 : nb) * BN;
        wn0 = isV ? 1024 + n0 : n0;
        Cp  = isV ? C2 : C;
    } else {
        n0 = blockIdx.x * BN; wn0 = n0; Cp = C;
    }

    u64t acc[RM/2][TN];
    #pragma unroll
    for (int i = 0; i < RM/2; i++)
        #pragma unroll
        for (int j = 0; j < TN; j++) acc[i][j] = 0ull;

    for (int kk = 0; kk < K; kk += 32) {
        /* A tile -> As[k][m] (transposed), pad 2 */
        #pragma unroll
        for (int it = 0; it < BM/32; it++) {
            int f = t + it*256;
            int am = f >> 3, ak = (f & 7)*4;
            float4 v4 = *(const float4*)(A + (size_t)(m0+am)*K + kk + ak);
            As[(ak+0)*LDA + am] = v4.x;
            As[(ak+1)*LDA + am] = v4.y;
            As[(ak+2)*LDA + am] = v4.z;
            As[(ak+3)*LDA + am] = v4.w;
        }
        /* W tile 32xBN -> Bs[k][n] */
        #pragma unroll
        for (int it = 0; it < BN/32; it++) {
            int f = t + it*256;
            int wk, wn;
            if (BN == 128) { wk = f >> 5; wn = (f & 31)*4; }
            else           { wk = f >> 4; wn = (f & 15)*4; }
            *(float4*)&Bs[wk*BN + wn] = *(const float4*)(W + (size_t)(kk+wk)*ldw + wn0 + wn);
        }
        __syncthreads();
        #pragma unroll
        for (int k = 0; k < 32; k++) {
            const float* arow = &As[k*LDA + tr*RM];
            u64t a2[RM/2];
            #pragma unroll
            for (int i = 0; i < RM/2; i++) a2[i] = *(const u64t*)(arow + 2*i);
            float bf[TN];
            #pragma unroll
            for (int jv = 0; jv < TN; jv += 4)
                *(float4*)&bf[jv] = *(const float4*)&Bs[k*BN + tc*TN + jv];
            #pragma unroll
            for (int j = 0; j < TN; j++) {
                u64t b2 = dup2(bf[j]);
                #pragma unroll
                for (int i = 0; i < RM/2; i++) fma2(acc[i][j], a2[i], b2);
            }
        }
        __syncthreads();
    }

    float bias4[TN];
    if (BIAS_) {
        #pragma unroll
        for (int jv = 0; jv < TN; jv += 4)
            *(float4*)&bias4[jv] = *(const float4*)(bias + n0 + tc*TN + jv);
    }
    #pragma unroll
    for (int i = 0; i < RM/2; i++) {
        float2 vals[TN];
        #pragma unroll
        for (int j = 0; j < TN; j++) vals[j] = unpack2(acc[i][j]);
        #pragma unroll
        for (int part = 0; part < 2; part++) {
            int m = m0 + tr*RM + 2*i + part;
            float* cp = Cp + (size_t)m*ldc + n0 + tc*TN;
            #pragma unroll
            for (int jv = 0; jv < TN; jv += 4) {
                float vv[4];
                #pragma unroll
                for (int j = 0; j < 4; j++) {
                    float x = part ? vals[jv+j].y : vals[jv+j].x;
                    if (BIAS_) x += bias4[jv+j];
                    if (GELU_) x = 0.5f*x*(1.0f + erff(x*0.70710678118654752f));
                    vv[j] = x;
                }
                if (ACC_) {
                    float4 old = *(float4*)(cp + jv);
                    vv[0]+=old.x; vv[1]+=old.y; vv[2]+=old.z; vv[3]+=old.w;
                }
                float4 r; r.x=vv[0]; r.y=vv[1]; r.z=vv[2]; r.w=vv[3];
                *(float4*)(cp + jv) = r;
            }
        }
    }
}

/* ---------------- fused attention per (batch', head) ----------------
   qT = (q * sqrt(dfm*SCALE)) transposed [d][n] in smem; v [n][d] in smem.
   16 warps, 8 query rows per warp, packed f32x2 dots + PV. Output written
   in-place over Q. */
#define NP  228
#define VP  68
#define PW  912
#define ATT_FLOATS (64*NP + NTOK*VP + 16*PW)
#define ATT_BYTES  (ATT_FLOATS*4)

__global__ void __launch_bounds__(512) attn_kernel() {
    extern __shared__ float sm[];
    float* qT   = sm;
    float* vsm  = sm + 64*NP;
    float* pbuf = vsm + NTOK*VP;

    int t = threadIdx.x;
    int w = t >> 5, lane = t & 31;
    int bh = blockIdx.x;
    int bp = bh >> 3, h = bh & 7;
    int bidx = bp & 63;
    float* Qb = g_Q + (size_t)bp*NTOK*INNER + h*DHEAD;
    const float* Vb = g_V + (size_t)bp*NTOK*INNER + h*DHEAD;

    /* load qT (scaled, transposed, cols 226..227 zeroed) and v */
    {
        int d4 = (t & 15)*4;
        float4 sd = *(const float4*)&g_sdfm[bidx*64 + d4];
        for (int f = t; f < NP*16; f += 512) {
            int n = f >> 4;
            float4 qv = make_float4(0.f,0.f,0.f,0.f);
            if (n < NTOK) qv = *(const float4*)(Qb + (size_t)n*INNER + d4);
            qT[(d4+0)*NP + n] = qv.x*sd.x;
            qT[(d4+1)*NP + n] = qv.y*sd.y;
            qT[(d4+2)*NP + n] = qv.z*sd.z;
            qT[(d4+3)*NP + n] = qv.w*sd.w;
        }
        for (int f = t; f < NTOK*16; f += 512) {
            int n = f >> 4;
            float4 vv = *(const float4*)(Vb + (size_t)n*INNER + d4);
            *(float4*)&vsm[n*VP + d4] = vv;
        }
    }
    __syncthreads();

    float* pw = pbuf + w*PW;

    for (int base = 0; base < 256; base += 128) {
        int i0 = base + w*8;
        if (i0 >= NTOK) continue;

        /* dots: 8 query rows (packed pairs) x 256 key cols */
        u64t acc[4][8];
        #pragma unroll
        for (int i = 0; i < 4; i++)
            #pragma unroll
            for (int j = 0; j < 8; j++) acc[i][j] = 0ull;

        #pragma unroll 2
        for (int d = 0; d < 64; d++) {
            const float* qrow = qT + d*NP;
            ulonglong2 qa = *(const ulonglong2*)(qrow + i0);
            ulonglong2 qb = *(const ulonglong2*)(qrow + i0 + 4);
            #pragma unroll
            for (int jj = 0; jj < 8; jj++) {
                u64t b2 = dup2(qrow[lane + 32*jj]);
                fma2(acc[0][jj], qa.x, b2);
                fma2(acc[1][jj], qa.y, b2);
                fma2(acc[2][jj], qb.x, b2);
                fma2(acc[3][jj], qb.y, b2);
            }
        }

        /* unpack to p[8][8] */
        float p[8][8];
        #pragma unroll
        for (int i = 0; i < 4; i++)
            #pragma unroll
            for (int jj = 0; jj < 8; jj++) {
                float2 u = unpack2(acc[i][jj]);
                p[2*i][jj] = u.x; p[2*i+1][jj] = u.y;
            }
        /* mask padded keys (jj==7, j=lane+224 >= 226) */
        if (lane >= 2) {
            #pragma unroll
            for (int ii = 0; ii < 8; ii++) p[ii][7] = -1e30f;
        }
        /* softmax per query row */
        #pragma unroll
        for (int ii = 0; ii < 8; ii++) {
            float mx = p[ii][0];
            #pragma unroll
            for (int jj = 1; jj < 8; jj++) mx = fmaxf(mx, p[ii][jj]);
            #pragma unroll
            for (int o = 16; o; o >>= 1) mx = fmaxf(mx, __shfl_xor_sync(0xffffffffu, mx, o));
            float s = 0.f;
            #pragma unroll
            for (int jj = 0; jj < 8; jj++) { float e = expf(p[ii][jj]-mx); p[ii][jj] = e; s += e; }
            #pragma unroll
            for (int o = 16; o; o >>= 1) s += __shfl_xor_sync(0xffffffffu, s, o);
            float inv = 1.0f/s;
            #pragma unroll
            for (int jj = 0; jj < 8; jj++) p[ii][jj] *= inv;
        }

        /* PV in two 4-row halves */
        #pragma unroll
        for (int half = 0; half < 2; half++) {
            #pragma unroll
            for (int jj = 0; jj < 8; jj++) {
                int j = lane + 32*jj;
                if (j < NTOK) {
                    #pragma unroll
                    for (int ii = 0; ii < 4; ii++) pw[j*4 + ii] = p[half*4 + ii][jj];
                }
            }
            __syncwarp();
            u64t o0[2] = {0ull, 0ull}, o1[2] = {0ull, 0ull};
            #pragma unroll 2
            for (int j = 0; j < NTOK; j++) {
                ulonglong2 pj = *(const ulonglong2*)&pw[j*4];
                u64t v0 = dup2(vsm[j*VP + lane]);
                u64t v1 = dup2(vsm[j*VP + 32 + lane]);
                fma2(o0[0], pj.x, v0); fma2(o0[1], pj.y, v0);
                fma2(o1[0], pj.x, v1); fma2(o1[1], pj.y, v1);
            }
            #pragma unroll
            for (int r = 0; r < 4; r++) {
                int i = i0 + half*4 + r;
                if (i < NTOK) {
                    float2 a = unpack2(o0[r/2]);
                    float2 b = unpack2(o1[r/2]);
                    Qb[(size_t)i*INNER + lane]      = (r & 1) ? a.y : a.x;
                    Qb[(size_t)i*INNER + 32 + lane] = (r & 1) ? b.y : b.x;
                }
            }
            __syncwarp();
        }
    }
}

/* ---------------- token exchange + final ---------------- */
__global__ void swap_cls_kernel() {
    int idx = blockIdx.x*blockDim.x + threadIdx.x;
    if (idx >= BATCH*64) return;
    int b = idx >> 6, c = idx & 63;
    size_t i0 = (size_t)b*NTOK*64 + c;
    size_t i1 = (size_t)(b+BATCH)*NTOK*64 + c;
    float a = g_X[i0], d = g_X[i1];
    g_X[i0] = d; g_X[i1] = a;
}

__global__ void final_kernel(float* __restrict__ out) {
    int idx = blockIdx.x*blockDim.x + threadIdx.x;
    if (idx >= BATCH*64) return;
    int b = idx >> 6, c = idx & 63;
    out[idx] = g_X[(size_t)b*NTOK*64 + c] + g_X[(size_t)(b+BATCH)*NTOK*64 + c];
}

/* ---------------- host orchestration ---------------- */
extern "C" void kernel_launch(void* const* d_in, const int* in_sizes, int n_in,
                              void* d_out, int out_size)
{
    const float* hsi       = (const float*)d_in[0];
    const float* lidar     = (const float*)d_in[1];
    const float* cls_hsi   = (const float*)d_in[2];
    const float* cls_lidar = (const float*)d_in[3];
    const float* pos_hsi   = (const float*)d_in[4];
    const float* pos_lidar = (const float*)d_in[5];
    const float* fmg_w     = (const float*)d_in[6];
    const float* ln1_g     = (const float*)d_in[7];
    const float* ln1_b     = (const float*)d_in[8];
    const float* qkv_w     = (const float*)d_in[9];
    const float* out_w     = (const float*)d_in[10];
    const float* out_b     = (const float*)d_in[11];
    const float* ln2_g     = (const float*)d_in[12];
    const float* ln2_b     = (const float*)d_in[13];
    const float* ff_w1     = (const float*)d_in[14];
    const float* ff_b1     = (const float*)d_in[15];
    const float* ff_w2     = (const float*)d_in[16];
    const float* ff_b2     = (const float*)d_in[17];

    float *X, *XN, *Q, *V, *H;
    cudaGetSymbolAddress((void**)&X,  g_X);
    cudaGetSymbolAddress((void**)&XN, g_XN);
    cudaGetSymbolAddress((void**)&Q,  g_Q);
    cudaGetSymbolAddress((void**)&V,  g_V);
    cudaGetSymbolAddress((void**)&H,  g_H);

    cudaFuncSetAttribute(attn_kernel, cudaFuncAttributeMaxDynamicSharedMemorySize, ATT_BYTES);

    mean_kernel<<<32, 256>>>(hsi, lidar);
    dfm_kernel<<<16, 256>>>(fmg_w);
    build_kernel<<<(M2*DIMC + 255)/256, 256>>>(hsi, cls_hsi, cls_lidar, pos_hsi, pos_lidar);

    for (int phase = 0; phase < 2; phase++) {
        for (int L = 0; L < DEPTH; L++) {
            ln_kernel<<<M2/8, 256>>>(X, XN, ln1_g + L*64, ln1_b + L*64);
            /* merged Q+V projection (K cols of qkv unused) */
            gemm_kernel<128,8,false,false,false,true><<<dim3(8,226), 256>>>(
                XN, qkv_w + (size_t)L*64*1536, nullptr, Q, V, 64, 1536, 512);
            attn_kernel<<<1024, 512, ATT_BYTES>>>();
            gemm_kernel<64,4,false,true,true,false><<<dim3(1,452), 256>>>(
                Q, out_w + (size_t)L*512*64, out_b + L*64, X, nullptr, 512, 64, 64);
            ln_kernel<<<M2/8, 256>>>(X, XN, ln2_g + L*64, ln2_b + L*64);
            gemm_kernel<128,8,true,false,true,false><<<dim3(2,226), 256>>>(
                XN, ff_w1 + (size_t)L*64*256, ff_b1 + L*256, H, nullptr, 64, 256, 256);
            gemm_kernel<64,4,false,true,true,false><<<dim3(1,452), 256>>>(
                H, ff_w2 + (size_t)L*256*64, ff_b2 + L*64, X, nullptr, 256, 64, 64);
        }
        if (phase == 0) swap_cls_kernel<<<16, 256>>>();
    }
    final_kernel<<<16, 256>>>((float*)d_out);
}

// round 4
// speedup vs baseline: 3.7708x; 2.0302x over previous
#include <cuda_runtime.h>
#include <cuda_bf16.h>
#include <math.h>
#include <cstdint>

#define BATCH   64
#define DIMC    64
#define HEADS   8
#define DHEAD   64
#define INNER   512
#define MLPD    256
#define DEPTH   4
#define NPATCH  225
#define NTOK    226
#define M2      (2*BATCH*NTOK)   /* 28928 rows (both branches) */
#define EPSV    1e-5f
#define SCALEV  0.125f           /* 64^-0.5 */

/* ---------------- packed f32x2 helpers ---------------- */
typedef unsigned long long u64t;

__device__ __forceinline__ u64t dup2(float x) {
    u64t r;
    asm("mov.b64 %0, {%1, %1};" : "=l"(r) : "r"(__float_as_uint(x)));
    return r;
}
__device__ __forceinline__ void fma2(u64t& d, u64t a, u64t b) {
    asm("fma.rn.f32x2 %0, %1, %2, %0;" : "+l"(d) : "l"(a), "l"(b));
}
__device__ __forceinline__ float2 unpack2(u64t v) {
    unsigned lo, hi;
    asm("mov.b64 {%0, %1}, %2;" : "=r"(lo), "=r"(hi) : "l"(v));
    return make_float2(__uint_as_float(lo), __uint_as_float(hi));
}

/* ---------------- mma.sync helpers (arch-portable sm_80+) ---------------- */
__device__ __forceinline__ uint32_t smem_u32(const void* p) {
    uint32_t a;
    asm("{ .reg .u64 t; cvta.to.shared.u64 t, %1; cvt.u32.u64 %0, t; }" : "=r"(a) : "l"(p));
    return a;
}
__device__ __forceinline__ void mma_bf16(float* c, const uint32_t* a, const uint32_t* b) {
    asm volatile("mma.sync.aligned.m16n8k16.row.col.f32.bf16.bf16.f32 "
        "{%0,%1,%2,%3}, {%4,%5,%6,%7}, {%8,%9}, {%0,%1,%2,%3};"
        : "+f"(c[0]), "+f"(c[1]), "+f"(c[2]), "+f"(c[3])
        : "r"(a[0]), "r"(a[1]), "r"(a[2]), "r"(a[3]), "r"(b[0]), "r"(b[1]));
}
__device__ __forceinline__ void ldm_x4_trans(uint32_t* r, uint32_t addr) {
    asm volatile("ldmatrix.sync.aligned.m8n8.x4.trans.shared.b16 {%0,%1,%2,%3}, [%4];"
        : "=r"(r[0]), "=r"(r[1]), "=r"(r[2]), "=r"(r[3]) : "r"(addr));
}
/* pack: low half = a, high half = b */
#define PACKBF(r, lo_, hi_) asm("cvt.rn.bf16x2.f32 %0, %1, %2;" : "=r"(r) : "f"(hi_), "f"(lo_))

/* ---------------- scratch (no allocs allowed) ---------------- */
__device__ float g_X [(size_t)M2*DIMC];
__device__ float g_XN[(size_t)M2*DIMC];
__device__ float g_Q [(size_t)M2*INNER];   /* also holds attention output in-place */
__device__ float g_V [(size_t)M2*INNER];
__device__ float g_H [(size_t)M2*MLPD];
__device__ float g_sdfm[BATCH*DIMC];       /* sqrt(sigmoid(..)*SCALE) */
__device__ float g_xmean[BATCH*2*DIMC];

/* ---------------- prologue kernels ---------------- */
__global__ void mean_kernel(const float* __restrict__ hsi, const float* __restrict__ lidar) {
    int idx = blockIdx.x*blockDim.x + threadIdx.x;
    if (idx >= BATCH*128) return;
    int b = idx >> 7, c = idx & 127;
    const float* src = (c < 64) ? (hsi   + ((size_t)b*64 + c)    *NPATCH)
                                : (lidar + ((size_t)b*64 + (c-64))*NPATCH);
    float s = 0.f;
    for (int p = 0; p < NPATCH; p++) s += src[p];
    g_xmean[idx] = s * (1.0f/NPATCH);
}

__global__ void dfm_kernel(const float* __restrict__ fmg_w) {
    int idx = blockIdx.x*blockDim.x + threadIdx.x;
    if (idx >= BATCH*64) return;
    int b = idx >> 6, d = idx & 63;
    const float* xm = g_xmean + b*128;
    const float* wc = fmg_w + d*65;
    float s = 0.f;
    for (int c = 0; c < 128; c++) s += xm[c] * wc[(size_t)c*4096];
    float sig = 1.0f/(1.0f + expf(-s));
    g_sdfm[idx] = sqrtf(sig * SCALEV);
}

__global__ void build_kernel(const float* __restrict__ hsi,
                             const float* __restrict__ cls_hsi, const float* __restrict__ cls_lidar,
                             const float* __restrict__ pos_hsi, const float* __restrict__ pos_lidar) {
    int idx = blockIdx.x*blockDim.x + threadIdx.x;
    if (idx >= M2*DIMC) return;
    int c  = idx & 63;
    int n  = (idx >> 6) % NTOK;
    int bp = idx / (NTOK*64);
    int b  = bp & 63;
    int br = bp >> 6;
    const float* cls = br ? cls_lidar : cls_hsi;
    const float* pos = br ? pos_lidar : pos_hsi;
    float v = (n == 0) ? cls[c] : hsi[((size_t)b*64 + c)*NPATCH + (n-1)];
    g_X[idx] = v + pos[n*64 + c];
}

/* ---------------- layernorm: one warp per row ---------------- */
__global__ void ln_kernel(const float* __restrict__ Xp, float* __restrict__ XNp,
                          const float* __restrict__ g, const float* __restrict__ bb) {
    int w = threadIdx.x >> 5, lane = threadIdx.x & 31;
    int row = blockIdx.x*8 + w;
    const float* xr = Xp + (size_t)row*64;
    float x0 = xr[lane], x1 = xr[lane+32];
    float s = x0 + x1;
    #pragma unroll
    for (int o = 16; o; o >>= 1) s += __shfl_xor_sync(0xffffffffu, s, o);
    float m = s * (1.0f/64.0f);
    float d0 = x0 - m, d1 = x1 - m;
    float v = d0*d0 + d1*d1;
    #pragma unroll
    for (int o = 16; o; o >>= 1) v += __shfl_xor_sync(0xffffffffu, v, o);
    float r = rsqrtf(v*(1.0f/64.0f) + EPSV);
    XNp[(size_t)row*64 + lane]      = d0*r*g[lane]    + bb[lane];
    XNp[(size_t)row*64 + lane + 32] = d1*r*g[lane+32] + bb[lane+32];
}

/* ---------------- tiled f32x2 GEMM (unchanged from R2) ---------------- */
template<int BM, int TN, bool GELU_, bool ACC_, bool BIAS_, bool QV_>
__global__ void __launch_bounds__(256) gemm_kernel(
    const float* __restrict__ A, const float* __restrict__ W,
    const float* __restrict__ bias, float* __restrict__ C, float* __restrict__ C2,
    int K, int ldw, int ldc)
{
    constexpr int BN  = 16*TN;
    constexpr int RM  = BM/16;
    constexpr int LDA = BM + 2;
    __shared__ float As[32*LDA];
    __shared__ float Bs[32*BN];
    int t  = threadIdx.x;
    int tc = t & 15;
    int tr = t >> 4;
    int m0 = blockIdx.y * BM;

    int n0, wn0;
    float* Cp;
    if (QV_) {
        int nb = blockIdx.x;
        bool isV = nb >= 4;
        n0  = (isV ? nb-4 : nb) * BN;
        wn0 = isV ? 1024 + n0 : n0;
        Cp  = isV ? C2 : C;
    } else {
        n0 = blockIdx.x * BN; wn0 = n0; Cp = C;
    }

    u64t acc[RM/2][TN];
    #pragma unroll
    for (int i = 0; i < RM/2; i++)
        #pragma unroll
        for (int j = 0; j < TN; j++) acc[i][j] = 0ull;

    for (int kk = 0; kk < K; kk += 32) {
        #pragma unroll
        for (int it = 0; it < BM/32; it++) {
            int f = t + it*256;
            int am = f >> 3, ak = (f & 7)*4;
            float4 v4 = *(const float4*)(A + (size_t)(m0+am)*K + kk + ak);
            As[(ak+0)*LDA + am] = v4.x;
            As[(ak+1)*LDA + am] = v4.y;
            As[(ak+2)*LDA + am] = v4.z;
            As[(ak+3)*LDA + am] = v4.w;
        }
        #pragma unroll
        for (int it = 0; it < BN/32; it++) {
            int f = t + it*256;
            int wk, wn;
            if (BN == 128) { wk = f >> 5; wn = (f & 31)*4; }
            else           { wk = f >> 4; wn = (f & 15)*4; }
            *(float4*)&Bs[wk*BN + wn] = *(const float4*)(W + (size_t)(kk+wk)*ldw + wn0 + wn);
        }
        __syncthreads();
        #pragma unroll
        for (int k = 0; k < 32; k++) {
            const float* arow = &As[k*LDA + tr*RM];
            u64t a2[RM/2];
            #pragma unroll
            for (int i = 0; i < RM/2; i++) a2[i] = *(const u64t*)(arow + 2*i);
            float bf[TN];
            #pragma unroll
            for (int jv = 0; jv < TN; jv += 4)
                *(float4*)&bf[jv] = *(const float4*)&Bs[k*BN + tc*TN + jv];
            #pragma unroll
            for (int j = 0; j < TN; j++) {
                u64t b2 = dup2(bf[j]);
                #pragma unroll
                for (int i = 0; i < RM/2; i++) fma2(acc[i][j], a2[i], b2);
            }
        }
        __syncthreads();
    }

    float bias4[TN];
    if (BIAS_) {
        #pragma unroll
        for (int jv = 0; jv < TN; jv += 4)
            *(float4*)&bias4[jv] = *(const float4*)(bias + n0 + tc*TN + jv);
    }
    #pragma unroll
    for (int i = 0; i < RM/2; i++) {
        float2 vals[TN];
        #pragma unroll
        for (int j = 0; j < TN; j++) vals[j] = unpack2(acc[i][j]);
        #pragma unroll
        for (int part = 0; part < 2; part++) {
            int m = m0 + tr*RM + 2*i + part;
            float* cp = Cp + (size_t)m*ldc + n0 + tc*TN;
            #pragma unroll
            for (int jv = 0; jv < TN; jv += 4) {
                float vv[4];
                #pragma unroll
                for (int j = 0; j < 4; j++) {
                    float x = part ? vals[jv+j].y : vals[jv+j].x;
                    if (BIAS_) x += bias4[jv+j];
                    if (GELU_) x = 0.5f*x*(1.0f + erff(x*0.70710678118654752f));
                    vv[j] = x;
                }
                if (ACC_) {
                    float4 old = *(float4*)(cp + jv);
                    vv[0]+=old.x; vv[1]+=old.y; vv[2]+=old.z; vv[3]+=old.w;
                }
                float4 r; r.x=vv[0]; r.y=vv[1]; r.z=vv[2]; r.w=vv[3];
                *(float4*)(cp + jv) = r;
            }
        }
    }
}

/* ---------------- bf16 mma.sync fused attention ----------------
   One CTA per (bp, h). 512 threads = 16 warps; warp w owns rows [16w, 16w+16).
   SMEM: Q bf16 [256 x 72] (rows 226-255 zero), V bf16 [256 x 72] (same).
   S = Qs*Qs^T in 64-col chunks; exp'd C-fragments repack directly into
   A-fragments for P*V (P never hits smem); 1/rowsum folded into epilogue.
   Output fp32 in-place over g_Q. */
#define QSTRIDE 72
#define QBYTES  (256*QSTRIDE*2)
#define ATT_BYTES (2*QBYTES)

__global__ void __launch_bounds__(512) attn_kernel() {
    extern __shared__ char smc[];
    uint16_t* Qh = (uint16_t*)smc;
    uint16_t* Vh = (uint16_t*)(smc + QBYTES);
    uint32_t vbase = smem_u32(smc) + QBYTES;

    int t = threadIdx.x;
    int bh = blockIdx.x;
    int bp = bh >> 3, h = bh & 7;
    int bidx = bp & 63;
    float* Qb = g_Q + (size_t)bp*NTOK*INNER + h*DHEAD;
    const float* Vb = g_V + (size_t)bp*NTOK*INNER + h*DHEAD;

    /* ---- stage Q (scaled) and V as bf16 ---- */
    {
        int d4 = (t & 15)*4;
        float4 sd = *(const float4*)&g_sdfm[bidx*64 + d4];
        for (int f = t; f < NTOK*16; f += 512) {
            int n = f >> 4;
            float4 q = *(const float4*)(Qb + (size_t)n*INNER + d4);
            q.x *= sd.x; q.y *= sd.y; q.z *= sd.z; q.w *= sd.w;
            uint32_t p0, p1;
            PACKBF(p0, q.x, q.y);
            PACKBF(p1, q.z, q.w);
            *(uint32_t*)&Qh[n*QSTRIDE + d4]     = p0;
            *(uint32_t*)&Qh[n*QSTRIDE + d4 + 2] = p1;
        }
        for (int f = t; f < NTOK*16; f += 512) {
            int n = f >> 4;
            float4 v = *(const float4*)(Vb + (size_t)n*INNER + d4);
            uint32_t p0, p1;
            PACKBF(p0, v.x, v.y);
            PACKBF(p1, v.z, v.w);
            *(uint32_t*)&Vh[n*QSTRIDE + d4]     = p0;
            *(uint32_t*)&Vh[n*QSTRIDE + d4 + 2] = p1;
        }
        /* zero rows 226..255 of both buffers */
        uint32_t* qz = (uint32_t*)(Qh + NTOK*QSTRIDE);
        uint32_t* vz = (uint32_t*)(Vh + NTOK*QSTRIDE);
        for (int f = t; f < (256 - NTOK)*QSTRIDE/2; f += 512) { qz[f] = 0u; vz[f] = 0u; }
    }
    __syncthreads();

    int lane = t & 31;
    int wid  = t >> 5;
    int m0   = wid*16;
    int r    = lane >> 2;
    int c2   = (lane & 3)*2;

    /* resident A-fragments of Q rows [m0, m0+16) */
    uint32_t qa[4][4];
    #pragma unroll
    for (int kb = 0; kb < 4; kb++) {
        const uint16_t* qrow = Qh + (m0 + r)*QSTRIDE + kb*16 + c2;
        qa[kb][0] = *(const uint32_t*)(qrow);
        qa[kb][1] = *(const uint32_t*)(qrow + 8*QSTRIDE);
        qa[kb][2] = *(const uint32_t*)(qrow + 8);
        qa[kb][3] = *(const uint32_t*)(qrow + 8*QSTRIDE + 8);
    }

    float O[8][4];
    #pragma unroll
    for (int nt = 0; nt < 8; nt++)
        #pragma unroll
        for (int j = 0; j < 4; j++) O[nt][j] = 0.f;
    float rs0 = 0.f, rs1 = 0.f;

    for (int ch = 0; ch < 4; ch++) {
        /* S chunk: 16 rows x 64 cols */
        float S[8][4];
        #pragma unroll
        for (int nt = 0; nt < 8; nt++)
            #pragma unroll
            for (int j = 0; j < 4; j++) S[nt][j] = 0.f;
        #pragma unroll
        for (int kb = 0; kb < 4; kb++) {
            #pragma unroll
            for (int nt = 0; nt < 8; nt++) {
                const uint16_t* brow = Qh + (ch*64 + nt*8 + r)*QSTRIDE + kb*16 + c2;
                uint32_t b[2] = { *(const uint32_t*)brow, *(const uint32_t*)(brow + 8) };
                mma_bf16(S[nt], qa[kb], b);
            }
        }
        /* exp + mask + pack into P A-fragments; accumulate rowsums */
        uint32_t pa[4][4];
        #pragma unroll
        for (int nt = 0; nt < 8; nt++) {
            int col = ch*64 + nt*8 + c2;
            float e0 = (col     < NTOK) ? __expf(S[nt][0]) : 0.f;
            float e1 = (col + 1 < NTOK) ? __expf(S[nt][1]) : 0.f;
            float e2 = (col     < NTOK) ? __expf(S[nt][2]) : 0.f;
            float e3 = (col + 1 < NTOK) ? __expf(S[nt][3]) : 0.f;
            rs0 += e0 + e1;
            rs1 += e2 + e3;
            uint32_t plo, phi;
            PACKBF(plo, e0, e1);
            PACKBF(phi, e2, e3);
            pa[nt >> 1][(nt & 1)*2]     = plo;
            pa[nt >> 1][(nt & 1)*2 + 1] = phi;
        }
        /* O += P_chunk * V_chunk */
        #pragma unroll
        for (int kb = 0; kb < 4; kb++) {
            uint32_t vb[16];
            int krow = ch*64 + kb*16 + (lane & 15);
            int coff = 8*(lane >> 4);
            #pragma unroll
            for (int q = 0; q < 4; q++)
                ldm_x4_trans(vb + q*4, vbase + (uint32_t)(krow*QSTRIDE + q*16 + coff)*2);
            #pragma unroll
            for (int nt = 0; nt < 8; nt++)
                mma_bf16(O[nt], pa[kb], &vb[(nt >> 1)*4 + (nt & 1)*2]);
        }
    }

    /* rowsum reduce over quad lanes, normalize, store in-place */
    #pragma unroll
    for (int o = 1; o <= 2; o <<= 1) {
        rs0 += __shfl_xor_sync(0xffffffffu, rs0, o);
        rs1 += __shfl_xor_sync(0xffffffffu, rs1, o);
    }
    float ri0 = 1.0f/rs0, ri1 = 1.0f/rs1;
    int i0 = m0 + r;
    if (i0 < NTOK) {
        float* op = Qb + (size_t)i0*INNER;
        #pragma unroll
        for (int nt = 0; nt < 8; nt++) {
            float2 v; v.x = O[nt][0]*ri0; v.y = O[nt][1]*ri0;
            *(float2*)(op + nt*8 + c2) = v;
        }
    }
    if (i0 + 8 < NTOK) {
        float* op = Qb + (size_t)(i0 + 8)*INNER;
        #pragma unroll
        for (int nt = 0; nt < 8; nt++) {
            float2 v; v.x = O[nt][2]*ri1; v.y = O[nt][3]*ri1;
            *(float2*)(op + nt*8 + c2) = v;
        }
    }
}

/* ---------------- token exchange + final ---------------- */
__global__ void swap_cls_kernel() {
    int idx = blockIdx.x*blockDim.x + threadIdx.x;
    if (idx >= BATCH*64) return;
    int b = idx >> 6, c = idx & 63;
    size_t i0 = (size_t)b*NTOK*64 + c;
    size_t i1 = (size_t)(b+BATCH)*NTOK*64 + c;
    float a = g_X[i0], d = g_X[i1];
    g_X[i0] = d; g_X[i1] = a;
}

__global__ void final_kernel(float* __restrict__ out) {
    int idx = blockIdx.x*blockDim.x + threadIdx.x;
    if (idx >= BATCH*64) return;
    int b = idx >> 6, c = idx & 63;
    out[idx] = g_X[(size_t)b*NTOK*64 + c] + g_X[(size_t)(b+BATCH)*NTOK*64 + c];
}

/* ---------------- host orchestration ---------------- */
extern "C" void kernel_launch(void* const* d_in, const int* in_sizes, int n_in,
                              void* d_out, int out_size)
{
    const float* hsi       = (const float*)d_in[0];
    const float* lidar     = (const float*)d_in[1];
    const float* cls_hsi   = (const float*)d_in[2];
    const float* cls_lidar = (const float*)d_in[3];
    const float* pos_hsi   = (const float*)d_in[4];
    const float* pos_lidar = (const float*)d_in[5];
    const float* fmg_w     = (const float*)d_in[6];
    const float* ln1_g     = (const float*)d_in[7];
    const float* ln1_b     = (const float*)d_in[8];
    const float* qkv_w     = (const float*)d_in[9];
    const float* out_w     = (const float*)d_in[10];
    const float* out_b     = (const float*)d_in[11];
    const float* ln2_g     = (const float*)d_in[12];
    const float* ln2_b     = (const float*)d_in[13];
    const float* ff_w1     = (const float*)d_in[14];
    const float* ff_b1     = (const float*)d_in[15];
    const float* ff_w2     = (const float*)d_in[16];
    const float* ff_b2     = (const float*)d_in[17];

    float *X, *XN, *Q, *V, *H;
    cudaGetSymbolAddress((void**)&X,  g_X);
    cudaGetSymbolAddress((void**)&XN, g_XN);
    cudaGetSymbolAddress((void**)&Q,  g_Q);
    cudaGetSymbolAddress((void**)&V,  g_V);
    cudaGetSymbolAddress((void**)&H,  g_H);

    cudaFuncSetAttribute(attn_kernel, cudaFuncAttributeMaxDynamicSharedMemorySize, ATT_BYTES);

    mean_kernel<<<32, 256>>>(hsi, lidar);
    dfm_kernel<<<16, 256>>>(fmg_w);
    build_kernel<<<(M2*DIMC + 255)/256, 256>>>(hsi, cls_hsi, cls_lidar, pos_hsi, pos_lidar);

    for (int phase = 0; phase < 2; phase++) {
        for (int L = 0; L < DEPTH; L++) {
            ln_kernel<<<M2/8, 256>>>(X, XN, ln1_g + L*64, ln1_b + L*64);
            gemm_kernel<128,8,false,false,false,true><<<dim3(8,226), 256>>>(
                XN, qkv_w + (size_t)L*64*1536, nullptr, Q, V, 64, 1536, 512);
            attn_kernel<<<1024, 512, ATT_BYTES>>>();
            gemm_kernel<64,4,false,true,true,false><<<dim3(1,452), 256>>>(
                Q, out_w + (size_t)L*512*64, out_b + L*64, X, nullptr, 512, 64, 64);
            ln_kernel<<<M2/8, 256>>>(X, XN, ln2_g + L*64, ln2_b + L*64);
            gemm_kernel<128,8,true,false,true,false><<<dim3(2,226), 256>>>(
                XN, ff_w1 + (size_t)L*64*256, ff_b1 + L*256, H, nullptr, 64, 256, 256);
            gemm_kernel<64,4,false,true,true,false><<<dim3(1,452), 256>>>(
                H, ff_w2 + (size_t)L*256*64, ff_b2 + L*64, X, nullptr, 256, 64, 64);
        }
        if (phase == 0) swap_cls_kernel<<<16, 256>>>();
    }
    final_kernel<<<16, 256>>>((float*)d_out);
}